// round 14
// baseline (speedup 1.0000x reference)
#include <cuda_runtime.h>
#include <cuda_bf16.h>
#include <math.h>
#include <stdint.h>

// Problem constants
#define MTOK   32768
#define DDIM   2048
#define NEXP   64
#define TOPK   8
#define NCOLS  128            // router(64) || noise(64)

// Tiling
#define BM      128           // tokens per CTA
#define KC      32            // K-chunk
#define NKB     (DDIM / KC)   // 64
#define NTHREADS 256          // 8 warps: 2(M) x 4(N)
#define LSTRIDE 133

// Fragment-order smem (uint32 = bf16x2 units):
//   A term: [s2][mt8][lane32][reg4] = 2048 u32 (8KB); 3 terms
//   B term: [s2][nt16][lane32][reg2] = 2048 u32 (8KB); 3 terms
#define TERM_U    2048
#define A_OFF_U   0
#define B_OFF_U   (3 * TERM_U)              // 6144
#define BUF_U     (6 * TERM_U)              // 12288 u32 = 49152 B
#define SMEM_TOTAL (2 * BUF_U * 4)          // 98304 B  (ls needs 34048 B)

// w fragment gmem: [term3][sg128][nt16][lane32][reg2] u32
#define WTERM_U   (128 * 16 * 32 * 2)       // 131072
__device__ uint32_t g_wf[3 * WTERM_U];

__device__ __forceinline__ void split3(float a, float b, uint32_t &ph, uint32_t &pm, uint32_t &pl) {
    __nv_bfloat162 h2 = __floats2bfloat162_rn(a, b);      // .x=a (low), .y=b (high)
    uint32_t hp = *(uint32_t*)&h2;
    float ha = __uint_as_float(hp << 16);
    float hb = __uint_as_float(hp & 0xFFFF0000u);
    float ra = a - ha, rb = b - hb;                        // exact
    __nv_bfloat162 m2 = __floats2bfloat162_rn(ra, rb);
    uint32_t mp = *(uint32_t*)&m2;
    float ma = __uint_as_float(mp << 16);
    float mb = __uint_as_float(mp & 0xFFFF0000u);
    __nv_bfloat162 l2 = __floats2bfloat162_rn(ra - ma, rb - mb);
    ph = hp; pm = mp; pl = *(uint32_t*)&l2;
}
__device__ __forceinline__ void mma_bf16(float* d, const uint32_t* a, const uint32_t* b) {
    asm volatile(
        "mma.sync.aligned.m16n8k16.row.col.f32.bf16.bf16.f32 "
        "{%0,%1,%2,%3}, {%4,%5,%6,%7}, {%8,%9}, {%0,%1,%2,%3};"
        : "+f"(d[0]), "+f"(d[1]), "+f"(d[2]), "+f"(d[3])
        : "r"(a[0]), "r"(a[1]), "r"(a[2]), "r"(a[3]), "r"(b[0]), "r"(b[1]));
}
__device__ __forceinline__ void cp16(uint32_t dst_smem, const void* src) {
    asm volatile("cp.async.ca.shared.global [%0], [%1], 16;\n" :: "r"(dst_smem), "l"(src));
}
__device__ __forceinline__ void cp_commit() { asm volatile("cp.async.commit_group;\n"); }
__device__ __forceinline__ void cp_wait()   { asm volatile("cp.async.wait_group 0;\n" ::: "memory"); }

// ---------------- w prep: 3-way bf16 split, fragment-order gmem ----------------
__global__ void wprep_kernel(const float* __restrict__ wr, const float* __restrict__ wn) {
    int id = blockIdx.x * blockDim.x + threadIdx.x;       // 0..131071 (k-pairs x n)
    if (id >= NCOLS * DDIM / 2) return;
    int n  = id >> 10;
    int k0 = (id & 1023) * 2;
    float w0 = (n < 64) ? wr[(size_t)k0 * 64 + n]       : wn[(size_t)k0 * 64 + (n - 64)];
    float w1 = (n < 64) ? wr[(size_t)(k0 + 1) * 64 + n] : wn[(size_t)(k0 + 1) * 64 + (n - 64)];
    uint32_t ph, pm, pl;
    split3(w0, w1, ph, pm, pl);
    int sg = k0 >> 4;
    int kp = k0 & 15;
    int reg = kp >> 3;
    int ln  = (n & 7) * 4 + ((kp >> 1) & 3);
    int nt  = n >> 3;
    size_t idx = (((size_t)sg * 16 + nt) * 32 + ln) * 2 + reg;
    g_wf[idx]               = ph;
    g_wf[WTERM_U + idx]     = pm;
    g_wf[2 * WTERM_U + idx] = pl;
}

// ---------------- main kernel ----------------
__global__ __launch_bounds__(NTHREADS, 1) void router_mma_kernel(
    const float* __restrict__ x,     const float* __restrict__ eps,
    const float* __restrict__ br,    const float* __restrict__ bn,
    const float* __restrict__ wskip, const float* __restrict__ bskip,
    float* __restrict__ out_router, float* __restrict__ out_idx,
    float* __restrict__ out_skip)
{
    extern __shared__ __align__(16) uint32_t smem[];
    float (*ls)[LSTRIDE] = (float(*)[LSTRIDE])smem;   // epilogue only (aliases buffers)
    uint32_t sbase;
    asm("{ .reg .u64 t; cvta.to.shared.u64 t, %1; cvt.u32.u64 %0, t; }" : "=r"(sbase) : "l"(smem));

    const int tid  = threadIdx.x;
    const int lane = tid & 31;
    const int wid  = tid >> 5;
    const int wm   = wid & 1;        // M half (rows wm*64..)
    const int wn_  = wid >> 1;       // N quarter (cols wn_*32..)
    const int m0   = blockIdx.x * BM;
    const int tok  = tid >> 1;       // conversion token 0..127
    const int kh   = (tid & 1) * 16; // k-half within chunk

    float master[4][4][4];           // outer accumulators (64 full-magnitude adds total)
    #pragma unroll
    for (int mt = 0; mt < 4; mt++)
        #pragma unroll
        for (int nt = 0; nt < 4; nt++)
            #pragma unroll
            for (int i = 0; i < 4; i++) master[mt][nt][i] = 0.f;
    float sk = 0.f;

    // ---- prologue: x(0) regs + skip partial, cp.async B(0) -> buf0 ----
    float4 xr[4];
    {
        const float* xp = x + (size_t)(m0 + tok) * DDIM + kh;
        const float* wp = wskip + kh;
        #pragma unroll
        for (int i = 0; i < 4; i++) {
            xr[i] = *(const float4*)(xp + i * 4);
            float4 w4 = *(const float4*)(wp + i * 4);
            sk = fmaf(xr[i].x, w4.x, fmaf(xr[i].y, w4.y, fmaf(xr[i].z, w4.z, fmaf(xr[i].w, w4.w, sk))));
        }
        #pragma unroll
        for (int i = 0; i < 6; i++) {            // 1536 cp16 of B (3 terms x 2048 u32)
            int fid = tid + i * NTHREADS;
            int t   = fid >> 9;
            int q   = fid & 511;
            const uint32_t* src = g_wf + (size_t)t * WTERM_U + q * 4;
            cp16(sbase + (uint32_t)((B_OFF_U + t * TERM_U + q * 4) * 4), src);
        }
        cp_commit();
    }

    // ================= chunk loop =================
    for (int kb = 0; kb < NKB; kb++) {
        const int cur = kb & 1;
        uint32_t* bufA = smem + (size_t)cur * BUF_U;

        // ---- convert x regs -> 3 bf16 A terms in buf[cur] ----
        {
            const int rr = tok & 15;
            const int mt = tok >> 4;
            #pragma unroll
            for (int i = 0; i < 4; i++) {
                float e[4] = {xr[i].x, xr[i].y, xr[i].z, xr[i].w};
                #pragma unroll
                for (int h = 0; h < 2; h++) {
                    int kk = kh + i * 4 + 2 * h;          // even
                    uint32_t ph, pm, pl;
                    split3(e[2 * h], e[2 * h + 1], ph, pm, pl);
                    int s    = kk >> 4;
                    int kp   = kk & 15;
                    int regk = kp >> 3;
                    int reg  = (regk << 1) | (rr >> 3);
                    int ln   = (rr & 7) * 4 + ((kp >> 1) & 3);
                    int idx  = ((s * 8 + mt) * 32 + ln) * 4 + reg;
                    bufA[idx]              = ph;
                    bufA[TERM_U + idx]     = pm;
                    bufA[2 * TERM_U + idx] = pl;
                }
            }
        }
        cp_wait();
        __syncthreads();     // buf[cur] A+B ready

        // ---- prefetch chunk kb+1 ----
        if (kb < NKB - 1) {
            const int k0 = (kb + 1) * KC;
            const float* xp = x + (size_t)(m0 + tok) * DDIM + k0 + kh;
            const float* wp = wskip + k0 + kh;
            #pragma unroll
            for (int i = 0; i < 4; i++) {
                xr[i] = *(const float4*)(xp + i * 4);
                float4 w4 = *(const float4*)(wp + i * 4);
                sk = fmaf(xr[i].x, w4.x, fmaf(xr[i].y, w4.y, fmaf(xr[i].z, w4.z, fmaf(xr[i].w, w4.w, sk))));
            }
            const uint32_t nxt = sbase + (uint32_t)((cur ^ 1) * BUF_U * 4);
            #pragma unroll
            for (int i = 0; i < 6; i++) {
                int fid = tid + i * NTHREADS;
                int t   = fid >> 9;
                int q   = fid & 511;
                const uint32_t* src = g_wf + (size_t)t * WTERM_U + (size_t)(kb + 1) * 2048 + q * 4;
                cp16(nxt + (uint32_t)((B_OFF_U + t * TERM_U + q * 4) * 4), src);
            }
            cp_commit();
        }

        // ---- MMA into chunk-local tmp (zeroed), then one fold into master ----
        float tmp[4][4][4];
        #pragma unroll
        for (int mt = 0; mt < 4; mt++)
            #pragma unroll
            for (int nt = 0; nt < 4; nt++)
                #pragma unroll
                for (int i = 0; i < 4; i++) tmp[mt][nt][i] = 0.f;

        const uint32_t* bufB = smem + (size_t)cur * BUF_U + B_OFF_U;
        #pragma unroll
        for (int s = 0; s < 2; s++) {
            uint32_t ah[4][4], am[4][4], al[4][4];
            uint32_t bh[4][2], bm[4][2], bl[4][2];
            #pragma unroll
            for (int mt = 0; mt < 4; mt++) {
                int aoff = ((s * 8 + wm * 4 + mt) * 32 + lane) * 4;
                *(uint4*)ah[mt] = *(const uint4*)(bufA + aoff);
                *(uint4*)am[mt] = *(const uint4*)(bufA + TERM_U + aoff);
                *(uint4*)al[mt] = *(const uint4*)(bufA + 2 * TERM_U + aoff);
            }
            #pragma unroll
            for (int nt = 0; nt < 4; nt++) {
                int boff = ((s * 16 + wn_ * 4 + nt) * 32 + lane) * 2;
                *(uint2*)bh[nt] = *(const uint2*)(bufB + boff);
                *(uint2*)bm[nt] = *(const uint2*)(bufB + TERM_U + boff);
                *(uint2*)bl[nt] = *(const uint2*)(bufB + 2 * TERM_U + boff);
            }
            // term-major: same-acc touches are 16 MMAs apart
            #pragma unroll
            for (int mt = 0; mt < 4; mt++)
                #pragma unroll
                for (int nt = 0; nt < 4; nt++) mma_bf16(tmp[mt][nt], ah[mt], bh[nt]);   // hh
            #pragma unroll
            for (int mt = 0; mt < 4; mt++)
                #pragma unroll
                for (int nt = 0; nt < 4; nt++) mma_bf16(tmp[mt][nt], ah[mt], bm[nt]);   // hm
            #pragma unroll
            for (int mt = 0; mt < 4; mt++)
                #pragma unroll
                for (int nt = 0; nt < 4; nt++) mma_bf16(tmp[mt][nt], am[mt], bh[nt]);   // mh
            #pragma unroll
            for (int mt = 0; mt < 4; mt++)
                #pragma unroll
                for (int nt = 0; nt < 4; nt++) mma_bf16(tmp[mt][nt], am[mt], bm[nt]);   // mm
            #pragma unroll
            for (int mt = 0; mt < 4; mt++)
                #pragma unroll
                for (int nt = 0; nt < 4; nt++) mma_bf16(tmp[mt][nt], ah[mt], bl[nt]);   // hl
            #pragma unroll
            for (int mt = 0; mt < 4; mt++)
                #pragma unroll
                for (int nt = 0; nt < 4; nt++) mma_bf16(tmp[mt][nt], al[mt], bh[nt]);   // lh
        }
        #pragma unroll
        for (int mt = 0; mt < 4; mt++)
            #pragma unroll
            for (int nt = 0; nt < 4; nt++)
                #pragma unroll
                for (int i = 0; i < 4; i++)
                    master[mt][nt][i] = __fadd_rn(master[mt][nt][i], tmp[mt][nt][i]);
        __syncthreads();     // all warps done with buf[cur]
    }

    // ---- stage logits (+bias) into ls ----
    #pragma unroll
    for (int mt = 0; mt < 4; mt++) {
        int r0 = wm * 64 + mt * 16 + (lane >> 2);
        #pragma unroll
        for (int nt = 0; nt < 4; nt++) {
            int c0 = wn_ * 32 + nt * 8 + (lane & 3) * 2;
            float b0 = (c0 < 64) ? __ldg(br + c0) : __ldg(bn + c0 - 64);
            float b1 = (c0 + 1 < 64) ? __ldg(br + c0 + 1) : __ldg(bn + c0 + 1 - 64);
            ls[r0][c0]         = __fadd_rn(master[mt][nt][0], b0);
            ls[r0][c0 + 1]     = __fadd_rn(master[mt][nt][1], b1);
            ls[r0 + 8][c0]     = __fadd_rn(master[mt][nt][2], b0);
            ls[r0 + 8][c0 + 1] = __fadd_rn(master[mt][nt][3], b1);
        }
    }
    // skip gate: combine half-token partials (lanes tid, tid^1)
    {
        float sko = __shfl_xor_sync(0xffffffffu, sk, 1);
        if ((tid & 1) == 0) ls[tok][128] = __fadd_rn(sk + sko, __ldg(bskip));
    }
    __syncthreads();

    // ---- noisy logits: 128 tok x 64 experts over 256 threads ----
    #pragma unroll
    for (int i = 0; i < 32; i++) {
        int fid = tid + i * NTHREADS;
        int tk = fid >> 6;
        int e  = fid & 63;
        float  lg = ls[tk][e];
        float  no = ls[tk][64 + e];
        double nd = (double)no;
        float  sp = (float)(fmax(nd, 0.0) + log1p(exp(-fabs(nd))));
        float  ev = __ldg(eps + (size_t)(m0 + tk) * NEXP + e);
        ls[tk][e] = __fadd_rn(lg, __fmul_rn(ev, sp));
    }
    __syncthreads();

    // ---- top-8 + softmax (one thread per token) ----
    if (tid < BM) {
        const int tk = tid;
        float vals[TOPK]; int idxs[TOPK];
        for (int k = 0; k < TOPK; k++) {
            float best = -3.402823466e38f; int bi = 0;
            for (int e = 0; e < NEXP; e++) {
                float v = ls[tk][e];
                if (v > best) { best = v; bi = e; }
            }
            vals[k] = best; idxs[k] = bi;
            ls[tk][bi] = -3.402823466e38f;
        }
        float mx = vals[0];
        float gsv[TOPK]; float s = 0.f;
        #pragma unroll
        for (int k = 0; k < TOPK; k++) { gsv[k] = expf(vals[k] - mx); s += gsv[k]; }
        float inv = 1.f / s;
        for (int e = 0; e < NEXP; e++) ls[tk][e] = 0.f;
        #pragma unroll
        for (int k = 0; k < TOPK; k++) ls[tk][idxs[k]] = gsv[k] * inv;
        #pragma unroll
        for (int k = 0; k < TOPK; k++) ls[tk][64 + k] = (float)idxs[k];
    }
    __syncthreads();

    // ---- cooperative coalesced stores ----
    #pragma unroll
    for (int i = 0; i < 32; i++) {
        int fid = tid + i * NTHREADS;
        int tk = fid >> 6;
        int e  = fid & 63;
        out_router[(size_t)(m0 + tk) * NEXP + e] = ls[tk][e];
    }
    #pragma unroll
    for (int i = 0; i < 4; i++) {
        int fid = tid + i * NTHREADS;
        int tk = fid >> 3;
        int k  = fid & 7;
        out_idx[(size_t)(m0 + tk) * TOPK + k] = ls[tk][64 + k];
    }
    if (tid < BM) {
        float z = ls[tid][128];
        out_skip[m0 + tid] = 1.f / (1.f + expf(-z));
    }
}

extern "C" void kernel_launch(void* const* d_in, const int* in_sizes, int n_in,
                              void* d_out, int out_size)
{
    const float* x     = (const float*)d_in[0];
    const float* eps   = (const float*)d_in[1];
    const float* wr    = (const float*)d_in[2];
    const float* br    = (const float*)d_in[3];
    const float* wn    = (const float*)d_in[4];
    const float* bn    = (const float*)d_in[5];
    const float* wskip = (const float*)d_in[6];
    const float* bskip = (const float*)d_in[7];

    float* out        = (float*)d_out;
    float* out_router = out;                                   // [32768, 64]
    float* out_idx    = out + (size_t)MTOK * NEXP;             // [32768, 8] as float
    float* out_skip   = out_idx + (size_t)MTOK * TOPK;         // [32768, 1]

    wprep_kernel<<<(NCOLS * DDIM / 2 + 255) / 256, 256>>>(wr, wn);

    cudaFuncSetAttribute(router_mma_kernel, cudaFuncAttributeMaxDynamicSharedMemorySize, SMEM_TOTAL);
    router_mma_kernel<<<MTOK / BM, NTHREADS, SMEM_TOTAL>>>(
        x, eps, br, bn, wskip, bskip, out_router, out_idx, out_skip);
}

// round 16
// speedup vs baseline: 1.0065x; 1.0065x over previous
#include <cuda_runtime.h>
#include <cuda_bf16.h>
#include <math.h>
#include <stdint.h>

// Problem constants
#define MTOK   32768
#define DDIM   2048
#define NEXP   64
#define TOPK   8
#define NCOLS  128            // router(64) || noise(64)

// Tiling
#define BM      128           // tokens per CTA
#define KC      32            // K-chunk
#define NKB     (DDIM / KC)   // 64
#define NTHREADS 256          // 8 warps: 2(M) x 4(N)
#define LSTRIDE 133

// Fragment-order smem (uint32 = bf16x2 units):
//   A term: [s2][mt8][lane32][reg4] = 2048 u32 (8KB); 3 terms
//   B term: [s2][nt16][lane32][reg2] = 2048 u32 (8KB); 3 terms
#define TERM_U    2048
#define A_OFF_U   0
#define B_OFF_U   (3 * TERM_U)              // 6144
#define BUF_U     (6 * TERM_U)              // 12288 u32 = 49152 B
#define SMEM_TOTAL (2 * BUF_U * 4)          // 98304 B  (ls needs 128*133*4 = 68096 B <= this)

// w fragment gmem: [term3][sg128][nt16][lane32][reg2] u32
#define WTERM_U   (128 * 16 * 32 * 2)       // 131072
__device__ uint32_t g_wf[3 * WTERM_U];

__device__ __forceinline__ void split3(float a, float b, uint32_t &ph, uint32_t &pm, uint32_t &pl) {
    __nv_bfloat162 h2 = __floats2bfloat162_rn(a, b);      // .x=a (low), .y=b (high)
    uint32_t hp = *(uint32_t*)&h2;
    float ha = __uint_as_float(hp << 16);
    float hb = __uint_as_float(hp & 0xFFFF0000u);
    float ra = a - ha, rb = b - hb;                        // exact
    __nv_bfloat162 m2 = __floats2bfloat162_rn(ra, rb);
    uint32_t mp = *(uint32_t*)&m2;
    float ma = __uint_as_float(mp << 16);
    float mb = __uint_as_float(mp & 0xFFFF0000u);
    __nv_bfloat162 l2 = __floats2bfloat162_rn(ra - ma, rb - mb);
    ph = hp; pm = mp; pl = *(uint32_t*)&l2;
}
__device__ __forceinline__ void mma_bf16(float* d, const uint32_t* a, const uint32_t* b) {
    asm volatile(
        "mma.sync.aligned.m16n8k16.row.col.f32.bf16.bf16.f32 "
        "{%0,%1,%2,%3}, {%4,%5,%6,%7}, {%8,%9}, {%0,%1,%2,%3};"
        : "+f"(d[0]), "+f"(d[1]), "+f"(d[2]), "+f"(d[3])
        : "r"(a[0]), "r"(a[1]), "r"(a[2]), "r"(a[3]), "r"(b[0]), "r"(b[1]));
}
__device__ __forceinline__ void cp16(uint32_t dst_smem, const void* src) {
    asm volatile("cp.async.ca.shared.global [%0], [%1], 16;\n" :: "r"(dst_smem), "l"(src));
}
__device__ __forceinline__ void cp_commit() { asm volatile("cp.async.commit_group;\n"); }
__device__ __forceinline__ void cp_wait()   { asm volatile("cp.async.wait_group 0;\n" ::: "memory"); }

// ---------------- w prep: 3-way bf16 split, fragment-order gmem ----------------
__global__ void wprep_kernel(const float* __restrict__ wr, const float* __restrict__ wn) {
    int id = blockIdx.x * blockDim.x + threadIdx.x;       // 0..131071 (k-pairs x n)
    if (id >= NCOLS * DDIM / 2) return;
    int n  = id >> 10;
    int k0 = (id & 1023) * 2;
    float w0 = (n < 64) ? wr[(size_t)k0 * 64 + n]       : wn[(size_t)k0 * 64 + (n - 64)];
    float w1 = (n < 64) ? wr[(size_t)(k0 + 1) * 64 + n] : wn[(size_t)(k0 + 1) * 64 + (n - 64)];
    uint32_t ph, pm, pl;
    split3(w0, w1, ph, pm, pl);
    int sg = k0 >> 4;
    int kp = k0 & 15;
    int reg = kp >> 3;
    int ln  = (n & 7) * 4 + ((kp >> 1) & 3);
    int nt  = n >> 3;
    size_t idx = (((size_t)sg * 16 + nt) * 32 + ln) * 2 + reg;
    g_wf[idx]               = ph;
    g_wf[WTERM_U + idx]     = pm;
    g_wf[2 * WTERM_U + idx] = pl;
}

// ---------------- main kernel ----------------
__global__ __launch_bounds__(NTHREADS, 1) void router_mma_kernel(
    const float* __restrict__ x,     const float* __restrict__ eps,
    const float* __restrict__ br,    const float* __restrict__ bn,
    const float* __restrict__ wskip, const float* __restrict__ bskip,
    float* __restrict__ out_router, float* __restrict__ out_idx,
    float* __restrict__ out_skip)
{
    extern __shared__ __align__(16) uint32_t smem[];
    float (*ls)[LSTRIDE] = (float(*)[LSTRIDE])smem;   // epilogue only (aliases buffers)
    uint32_t sbase;
    asm("{ .reg .u64 t; cvta.to.shared.u64 t, %1; cvt.u32.u64 %0, t; }" : "=r"(sbase) : "l"(smem));

    const int tid  = threadIdx.x;
    const int lane = tid & 31;
    const int wid  = tid >> 5;
    const int wm   = wid & 1;        // M half (rows wm*64..)
    const int wn_  = wid >> 1;       // N quarter (cols wn_*32..)
    const int m0   = blockIdx.x * BM;
    const int tok  = tid >> 1;       // conversion token 0..127
    const int kh   = (tid & 1) * 16; // k-half within chunk

    float master[4][4][4];
    #pragma unroll
    for (int mt = 0; mt < 4; mt++)
        #pragma unroll
        for (int nt = 0; nt < 4; nt++)
            #pragma unroll
            for (int i = 0; i < 4; i++) master[mt][nt][i] = 0.f;
    float sk = 0.f;

    const int rr = tok & 15;
    const int amt = tok >> 4;

    // ---- prologue: convert chunk 0 into buf0; prefetch x(1) ----
    float4 xr[4];
    {
        const float* xp = x + (size_t)(m0 + tok) * DDIM + kh;
        const float* wp = wskip + kh;
        #pragma unroll
        for (int i = 0; i < 4; i++) {
            xr[i] = *(const float4*)(xp + i * 4);
            float4 w4 = *(const float4*)(wp + i * 4);
            sk = fmaf(xr[i].x, w4.x, fmaf(xr[i].y, w4.y, fmaf(xr[i].z, w4.z, fmaf(xr[i].w, w4.w, sk))));
        }
        #pragma unroll
        for (int i = 0; i < 6; i++) {            // B(0): 1536 cp16
            int fid = tid + i * NTHREADS;
            int t   = fid >> 9;
            int q   = fid & 511;
            const uint32_t* src = g_wf + (size_t)t * WTERM_U + q * 4;
            cp16(sbase + (uint32_t)((B_OFF_U + t * TERM_U + q * 4) * 4), src);
        }
        cp_commit();
        // convert x(0) -> A(0) in buf0
        #pragma unroll
        for (int i = 0; i < 4; i++) {
            float e[4] = {xr[i].x, xr[i].y, xr[i].z, xr[i].w};
            #pragma unroll
            for (int h = 0; h < 2; h++) {
                int kk = kh + i * 4 + 2 * h;
                uint32_t ph, pm, pl;
                split3(e[2 * h], e[2 * h + 1], ph, pm, pl);
                int s    = kk >> 4;
                int kp   = kk & 15;
                int reg  = ((kp >> 3) << 1) | (rr >> 3);
                int ln   = (rr & 7) * 4 + ((kp >> 1) & 3);
                int idx  = ((s * 8 + amt) * 32 + ln) * 4 + reg;
                smem[idx]              = ph;
                smem[TERM_U + idx]     = pm;
                smem[2 * TERM_U + idx] = pl;
            }
        }
        // prefetch x(1)
        const float* xp1 = x + (size_t)(m0 + tok) * DDIM + KC + kh;
        const float* wp1 = wskip + KC + kh;
        #pragma unroll
        for (int i = 0; i < 4; i++) {
            xr[i] = *(const float4*)(xp1 + i * 4);
            float4 w4 = *(const float4*)(wp1 + i * 4);
            sk = fmaf(xr[i].x, w4.x, fmaf(xr[i].y, w4.y, fmaf(xr[i].z, w4.z, fmaf(xr[i].w, w4.w, sk))));
        }
        cp_wait();
    }
    __syncthreads();

    // ================= chunk loop: ONE barrier per chunk =================
    // Invariant at top of iter kb: buf[cur] holds A(kb),B(kb); xr holds x(kb+1).
    // This iter reads only buf[cur], writes only buf[cur^1].
    for (int kb = 0; kb < NKB; kb++) {
        const int cur = kb & 1;
        uint32_t* bufA = smem + (size_t)cur * BUF_U;
        const uint32_t* bufB = bufA + B_OFF_U;
        uint32_t* bufN = smem + (size_t)(cur ^ 1) * BUF_U;

        // ---- issue cp.async B(kb+1) -> buf[cur^1] (overlaps the MMAs below) ----
        if (kb < NKB - 1) {
            const uint32_t nxt = sbase + (uint32_t)((cur ^ 1) * BUF_U * 4);
            #pragma unroll
            for (int i = 0; i < 6; i++) {
                int fid = tid + i * NTHREADS;
                int t   = fid >> 9;
                int q   = fid & 511;
                const uint32_t* src = g_wf + (size_t)t * WTERM_U + (size_t)(kb + 1) * 2048 + q * 4;
                cp16(nxt + (uint32_t)((B_OFF_U + t * TERM_U + q * 4) * 4), src);
            }
            cp_commit();
        }

        // ---- MMA(kb) into chunk-local tmp ----
        float tmp[4][4][4];
        #pragma unroll
        for (int mt = 0; mt < 4; mt++)
            #pragma unroll
            for (int nt = 0; nt < 4; nt++)
                #pragma unroll
                for (int i = 0; i < 4; i++) tmp[mt][nt][i] = 0.f;

        #pragma unroll
        for (int s = 0; s < 2; s++) {
            uint32_t ah[4][4], am[4][4], al[4][4];
            uint32_t bh[4][2], bm[4][2], bl[4][2];
            #pragma unroll
            for (int mt = 0; mt < 4; mt++) {
                int aoff = ((s * 8 + wm * 4 + mt) * 32 + lane) * 4;
                *(uint4*)ah[mt] = *(const uint4*)(bufA + aoff);
                *(uint4*)am[mt] = *(const uint4*)(bufA + TERM_U + aoff);
                *(uint4*)al[mt] = *(const uint4*)(bufA + 2 * TERM_U + aoff);
            }
            #pragma unroll
            for (int nt = 0; nt < 4; nt++) {
                int boff = ((s * 16 + wn_ * 4 + nt) * 32 + lane) * 2;
                *(uint2*)bh[nt] = *(const uint2*)(bufB + boff);
                *(uint2*)bm[nt] = *(const uint2*)(bufB + TERM_U + boff);
                *(uint2*)bl[nt] = *(const uint2*)(bufB + 2 * TERM_U + boff);
            }
            #pragma unroll
            for (int mt = 0; mt < 4; mt++)
                #pragma unroll
                for (int nt = 0; nt < 4; nt++) mma_bf16(tmp[mt][nt], ah[mt], bh[nt]);   // hh
            #pragma unroll
            for (int mt = 0; mt < 4; mt++)
                #pragma unroll
                for (int nt = 0; nt < 4; nt++) mma_bf16(tmp[mt][nt], ah[mt], bm[nt]);   // hm
            #pragma unroll
            for (int mt = 0; mt < 4; mt++)
                #pragma unroll
                for (int nt = 0; nt < 4; nt++) mma_bf16(tmp[mt][nt], am[mt], bh[nt]);   // mh
            #pragma unroll
            for (int mt = 0; mt < 4; mt++)
                #pragma unroll
                for (int nt = 0; nt < 4; nt++) mma_bf16(tmp[mt][nt], am[mt], bm[nt]);   // mm
            #pragma unroll
            for (int mt = 0; mt < 4; mt++)
                #pragma unroll
                for (int nt = 0; nt < 4; nt++) mma_bf16(tmp[mt][nt], ah[mt], bl[nt]);   // hl
            #pragma unroll
            for (int mt = 0; mt < 4; mt++)
                #pragma unroll
                for (int nt = 0; nt < 4; nt++) mma_bf16(tmp[mt][nt], al[mt], bh[nt]);   // lh
        }

        // ---- convert xr = x(kb+1) -> A(kb+1) in buf[cur^1] (overlaps HMMA drain) ----
        if (kb < NKB - 1) {
            #pragma unroll
            for (int i = 0; i < 4; i++) {
                float e[4] = {xr[i].x, xr[i].y, xr[i].z, xr[i].w};
                #pragma unroll
                for (int h = 0; h < 2; h++) {
                    int kk = kh + i * 4 + 2 * h;
                    uint32_t ph, pm, pl;
                    split3(e[2 * h], e[2 * h + 1], ph, pm, pl);
                    int s    = kk >> 4;
                    int kp   = kk & 15;
                    int reg  = ((kp >> 3) << 1) | (rr >> 3);
                    int ln   = (rr & 7) * 4 + ((kp >> 1) & 3);
                    int idx  = ((s * 8 + amt) * 32 + ln) * 4 + reg;
                    bufN[idx]              = ph;
                    bufN[TERM_U + idx]     = pm;
                    bufN[2 * TERM_U + idx] = pl;
                }
            }
        }
        // ---- prefetch x(kb+2) ----
        if (kb < NKB - 2) {
            const int k0 = (kb + 2) * KC;
            const float* xp = x + (size_t)(m0 + tok) * DDIM + k0 + kh;
            const float* wp = wskip + k0 + kh;
            #pragma unroll
            for (int i = 0; i < 4; i++) {
                xr[i] = *(const float4*)(xp + i * 4);
                float4 w4 = *(const float4*)(wp + i * 4);
                sk = fmaf(xr[i].x, w4.x, fmaf(xr[i].y, w4.y, fmaf(xr[i].z, w4.z, fmaf(xr[i].w, w4.w, sk))));
            }
        }
        // ---- fold tmp -> master (after convert: hides HMMA latency) ----
        #pragma unroll
        for (int mt = 0; mt < 4; mt++)
            #pragma unroll
            for (int nt = 0; nt < 4; nt++)
                #pragma unroll
                for (int i = 0; i < 4; i++)
                    master[mt][nt][i] = __fadd_rn(master[mt][nt][i], tmp[mt][nt][i]);

        if (kb < NKB - 1) cp_wait();
        __syncthreads();
    }

    // ---- stage logits (+bias) into ls ----
    #pragma unroll
    for (int mt = 0; mt < 4; mt++) {
        int r0 = wm * 64 + mt * 16 + (lane >> 2);
        #pragma unroll
        for (int nt = 0; nt < 4; nt++) {
            int c0 = wn_ * 32 + nt * 8 + (lane & 3) * 2;
            float b0 = (c0 < 64) ? __ldg(br + c0) : __ldg(bn + c0 - 64);
            float b1 = (c0 + 1 < 64) ? __ldg(br + c0 + 1) : __ldg(bn + c0 + 1 - 64);
            ls[r0][c0]         = __fadd_rn(master[mt][nt][0], b0);
            ls[r0][c0 + 1]     = __fadd_rn(master[mt][nt][1], b1);
            ls[r0 + 8][c0]     = __fadd_rn(master[mt][nt][2], b0);
            ls[r0 + 8][c0 + 1] = __fadd_rn(master[mt][nt][3], b1);
        }
    }
    // skip gate: combine half-token partials (lanes tid, tid^1)
    {
        float sko = __shfl_xor_sync(0xffffffffu, sk, 1);
        if ((tid & 1) == 0) ls[tok][128] = __fadd_rn(sk + sko, __ldg(bskip));
    }
    __syncthreads();

    // ---- noisy logits: 128 tok x 64 experts over 256 threads ----
    #pragma unroll
    for (int i = 0; i < 32; i++) {
        int fid = tid + i * NTHREADS;
        int tk = fid >> 6;
        int e  = fid & 63;
        float  lg = ls[tk][e];
        float  no = ls[tk][64 + e];
        double nd = (double)no;
        float  sp = (float)(fmax(nd, 0.0) + log1p(exp(-fabs(nd))));
        float  ev = __ldg(eps + (size_t)(m0 + tk) * NEXP + e);
        ls[tk][e] = __fadd_rn(lg, __fmul_rn(ev, sp));
    }
    __syncthreads();

    // ---- top-8 + softmax (one thread per token) ----
    if (tid < BM) {
        const int tk = tid;
        float vals[TOPK]; int idxs[TOPK];
        for (int k = 0; k < TOPK; k++) {
            float best = -3.402823466e38f; int bi = 0;
            for (int e = 0; e < NEXP; e++) {
                float v = ls[tk][e];
                if (v > best) { best = v; bi = e; }
            }
            vals[k] = best; idxs[k] = bi;
            ls[tk][bi] = -3.402823466e38f;
        }
        float mx = vals[0];
        float gsv[TOPK]; float s = 0.f;
        #pragma unroll
        for (int k = 0; k < TOPK; k++) { gsv[k] = expf(vals[k] - mx); s += gsv[k]; }
        float inv = 1.f / s;
        for (int e = 0; e < NEXP; e++) ls[tk][e] = 0.f;
        #pragma unroll
        for (int k = 0; k < TOPK; k++) ls[tk][idxs[k]] = gsv[k] * inv;
        #pragma unroll
        for (int k = 0; k < TOPK; k++) ls[tk][64 + k] = (float)idxs[k];
    }
    __syncthreads();

    // ---- cooperative coalesced stores ----
    #pragma unroll
    for (int i = 0; i < 32; i++) {
        int fid = tid + i * NTHREADS;
        int tk = fid >> 6;
        int e  = fid & 63;
        out_router[(size_t)(m0 + tk) * NEXP + e] = ls[tk][e];
    }
    #pragma unroll
    for (int i = 0; i < 4; i++) {
        int fid = tid + i * NTHREADS;
        int tk = fid >> 3;
        int k  = fid & 7;
        out_idx[(size_t)(m0 + tk) * TOPK + k] = ls[tk][64 + k];
    }
    if (tid < BM) {
        float z = ls[tid][128];
        out_skip[m0 + tid] = 1.f / (1.f + expf(-z));
    }
}

extern "C" void kernel_launch(void* const* d_in, const int* in_sizes, int n_in,
                              void* d_out, int out_size)
{
    const float* x     = (const float*)d_in[0];
    const float* eps   = (const float*)d_in[1];
    const float* wr    = (const float*)d_in[2];
    const float* br    = (const float*)d_in[3];
    const float* wn    = (const float*)d_in[4];
    const float* bn    = (const float*)d_in[5];
    const float* wskip = (const float*)d_in[6];
    const float* bskip = (const float*)d_in[7];

    float* out        = (float*)d_out;
    float* out_router = out;                                   // [32768, 64]
    float* out_idx    = out + (size_t)MTOK * NEXP;             // [32768, 8] as float
    float* out_skip   = out_idx + (size_t)MTOK * TOPK;         // [32768, 1]

    wprep_kernel<<<(NCOLS * DDIM / 2 + 255) / 256, 256>>>(wr, wn);

    cudaFuncSetAttribute(router_mma_kernel, cudaFuncAttributeMaxDynamicSharedMemorySize, SMEM_TOTAL);
    router_mma_kernel<<<MTOK / BM, NTHREADS, SMEM_TOTAL>>>(
        x, eps, br, bn, wskip, bskip, out_router, out_idx, out_skip);
}

// round 17
// speedup vs baseline: 1.4670x; 1.4574x over previous
#include <cuda_runtime.h>
#include <cuda_fp16.h>
#include <math.h>
#include <stdint.h>

// Problem constants
#define MTOK   32768
#define DDIM   2048
#define NEXP   64
#define TOPK   8
#define NCOLS  128            // router(64) || noise(64)

// Tiling
#define BM      64            // tokens per CTA
#define KC      32            // K-chunk
#define NKB     (DDIM / KC)   // 64
#define NTHREADS 256          // 8 warps: 2(M) x 4(N), warp tile 32x32
#define LSTRIDE 133

// Fragment-order smem (uint32 = fp16x2 units):
//   A term: [s2][mt4][lane32][reg4] = 1024 u32 (4KB); 2 terms
//   B term: [s2][nt16][lane32][reg2] = 2048 u32 (8KB); 2 terms
#define ATERM_U   1024
#define BTERM_U   2048
#define B_OFF_U   (2 * ATERM_U)             // 2048
#define BUF_U     (2 * ATERM_U + 2 * BTERM_U)  // 6144 u32 = 24KB
#define SMEM_TOTAL (2 * BUF_U * 4)          // 49152 B (ls needs 64*133*4 = 34048 <= this)

// w fragment gmem: [term2][sg128][nt16][lane32][reg2] u32
#define WTERM_U   (128 * 16 * 32 * 2)       // 131072
__device__ uint32_t g_wf[2 * WTERM_U];

// Exact power-of-2 scaling keeps fp16 split terms in normal range.
#define XSCL  64.0f
#define WSCL  4096.0f
#define INV_SCL (1.0f / (64.0f * 4096.0f))  // 2^-18

__device__ __forceinline__ void split2(float a, float b, uint32_t &hp, uint32_t &lp) {
    __half2 h2 = __floats2half2_rn(a, b);          // .x=a(low), .y=b(high)
    float ha = __low2float(h2);
    float hb = __high2float(h2);
    __half2 l2 = __floats2half2_rn(a - ha, b - hb);
    hp = *(uint32_t*)&h2;
    lp = *(uint32_t*)&l2;
}
__device__ __forceinline__ void mma_f16(float* d, const uint32_t* a, const uint32_t* b) {
    asm volatile(
        "mma.sync.aligned.m16n8k16.row.col.f32.f16.f16.f32 "
        "{%0,%1,%2,%3}, {%4,%5,%6,%7}, {%8,%9}, {%0,%1,%2,%3};"
        : "+f"(d[0]), "+f"(d[1]), "+f"(d[2]), "+f"(d[3])
        : "r"(a[0]), "r"(a[1]), "r"(a[2]), "r"(a[3]), "r"(b[0]), "r"(b[1]));
}
__device__ __forceinline__ void cp16(uint32_t dst_smem, const void* src) {
    asm volatile("cp.async.ca.shared.global [%0], [%1], 16;\n" :: "r"(dst_smem), "l"(src));
}
__device__ __forceinline__ void cp_commit() { asm volatile("cp.async.commit_group;\n"); }
__device__ __forceinline__ void cp_wait()   { asm volatile("cp.async.wait_group 0;\n" ::: "memory"); }

// ---------------- w prep: scale by 4096, 2-level fp16 split, fragment-order gmem ----------------
__global__ void wprep_kernel(const float* __restrict__ wr, const float* __restrict__ wn) {
    int id = blockIdx.x * blockDim.x + threadIdx.x;       // 0..131071 (k-pairs x n)
    if (id >= NCOLS * DDIM / 2) return;
    int n  = id >> 10;
    int k0 = (id & 1023) * 2;
    float w0 = ((n < 64) ? wr[(size_t)k0 * 64 + n]       : wn[(size_t)k0 * 64 + (n - 64)]) * WSCL;
    float w1 = ((n < 64) ? wr[(size_t)(k0 + 1) * 64 + n] : wn[(size_t)(k0 + 1) * 64 + (n - 64)]) * WSCL;
    uint32_t hp, lp;
    split2(w0, w1, hp, lp);
    int sg  = k0 >> 4;
    int kp  = k0 & 15;
    int reg = kp >> 3;
    int ln  = (n & 7) * 4 + ((kp >> 1) & 3);
    int nt  = n >> 3;
    size_t idx = (((size_t)sg * 16 + nt) * 32 + ln) * 2 + reg;
    g_wf[idx]           = hp;
    g_wf[WTERM_U + idx] = lp;
}

// ---------------- main kernel ----------------
__global__ __launch_bounds__(NTHREADS, 2) void router_mma_kernel(
    const float* __restrict__ x,     const float* __restrict__ eps,
    const float* __restrict__ br,    const float* __restrict__ bn,
    const float* __restrict__ wskip, const float* __restrict__ bskip,
    float* __restrict__ out_router, float* __restrict__ out_idx,
    float* __restrict__ out_skip)
{
    extern __shared__ __align__(16) uint32_t smem[];
    float (*ls)[LSTRIDE] = (float(*)[LSTRIDE])smem;   // epilogue only (aliases buffers)
    uint32_t sbase;
    asm("{ .reg .u64 t; cvta.to.shared.u64 t, %1; cvt.u32.u64 %0, t; }" : "=r"(sbase) : "l"(smem));

    const int tid  = threadIdx.x;
    const int lane = tid & 31;
    const int wid  = tid >> 5;
    const int wm   = wid & 1;        // M half (rows wm*32..)
    const int wn_  = wid >> 1;       // N quarter (cols wn_*32..)
    const int m0   = blockIdx.x * BM;
    const int tok  = tid >> 2;       // conversion token 0..63
    const int kq   = (tid & 3) * 8;  // k-offset within chunk (8 elems per thread)

    float master[2][4][4];
    #pragma unroll
    for (int mt = 0; mt < 2; mt++)
        #pragma unroll
        for (int nt = 0; nt < 4; nt++)
            #pragma unroll
            for (int i = 0; i < 4; i++) master[mt][nt][i] = 0.f;
    float sk = 0.f;

    const int rr  = tok & 15;
    const int amt = tok >> 4;        // m16 tile 0..3

    // ---- prologue: convert chunk 0 into buf0; prefetch x(1) ----
    float4 xr[2];
    {
        const float* xp = x + (size_t)(m0 + tok) * DDIM + kq;
        const float* wp = wskip + kq;
        #pragma unroll
        for (int i = 0; i < 2; i++) {
            xr[i] = *(const float4*)(xp + i * 4);
            float4 w4 = *(const float4*)(wp + i * 4);
            sk = fmaf(xr[i].x, w4.x, fmaf(xr[i].y, w4.y, fmaf(xr[i].z, w4.z, fmaf(xr[i].w, w4.w, sk))));
        }
        #pragma unroll
        for (int i = 0; i < 4; i++) {            // B(0): 1024 cp16
            int fid = tid + i * NTHREADS;
            int t   = fid >> 9;
            int q   = fid & 511;
            const uint32_t* src = g_wf + (size_t)t * WTERM_U + q * 4;
            cp16(sbase + (uint32_t)((B_OFF_U + t * BTERM_U + q * 4) * 4), src);
        }
        cp_commit();
        // convert x(0) -> A(0) in buf0
        #pragma unroll
        for (int i = 0; i < 2; i++) {
            float e[4] = {xr[i].x, xr[i].y, xr[i].z, xr[i].w};
            #pragma unroll
            for (int h = 0; h < 2; h++) {
                int kk = kq + i * 4 + 2 * h;
                uint32_t hp, lp;
                split2(e[2 * h] * XSCL, e[2 * h + 1] * XSCL, hp, lp);
                int s   = kk >> 4;
                int kp  = kk & 15;
                int reg = ((kp >> 3) << 1) | (rr >> 3);
                int ln  = (rr & 7) * 4 + ((kp >> 1) & 3);
                int idx = ((s * 4 + amt) * 32 + ln) * 4 + reg;
                smem[idx]           = hp;
                smem[ATERM_U + idx] = lp;
            }
        }
        // prefetch x(1)
        const float* xp1 = x + (size_t)(m0 + tok) * DDIM + KC + kq;
        const float* wp1 = wskip + KC + kq;
        #pragma unroll
        for (int i = 0; i < 2; i++) {
            xr[i] = *(const float4*)(xp1 + i * 4);
            float4 w4 = *(const float4*)(wp1 + i * 4);
            sk = fmaf(xr[i].x, w4.x, fmaf(xr[i].y, w4.y, fmaf(xr[i].z, w4.z, fmaf(xr[i].w, w4.w, sk))));
        }
        cp_wait();
    }
    __syncthreads();

    // ================= chunk loop: ONE barrier per chunk =================
    // Invariant at top of iter kb: buf[cur] holds A(kb),B(kb); xr holds x(kb+1).
    for (int kb = 0; kb < NKB; kb++) {
        const int cur = kb & 1;
        uint32_t* bufA = smem + (size_t)cur * BUF_U;
        const uint32_t* bufB = bufA + B_OFF_U;
        uint32_t* bufN = smem + (size_t)(cur ^ 1) * BUF_U;

        // ---- cp.async B(kb+1) -> buf[cur^1] ----
        if (kb < NKB - 1) {
            const uint32_t nxt = sbase + (uint32_t)((cur ^ 1) * BUF_U * 4);
            #pragma unroll
            for (int i = 0; i < 4; i++) {
                int fid = tid + i * NTHREADS;
                int t   = fid >> 9;
                int q   = fid & 511;
                const uint32_t* src = g_wf + (size_t)t * WTERM_U + (size_t)(kb + 1) * 2048 + q * 4;
                cp16(nxt + (uint32_t)((B_OFF_U + t * BTERM_U + q * 4) * 4), src);
            }
            cp_commit();
        }

        // ---- MMA(kb): 2 k-steps x 3 terms x 2mt x 4nt = 48 HMMA ----
        float tmp[2][4][4];
        #pragma unroll
        for (int mt = 0; mt < 2; mt++)
            #pragma unroll
            for (int nt = 0; nt < 4; nt++)
                #pragma unroll
                for (int i = 0; i < 4; i++) tmp[mt][nt][i] = 0.f;

        #pragma unroll
        for (int s = 0; s < 2; s++) {
            uint32_t ah[2][4], al[2][4], bh[4][2], bl[4][2];
            #pragma unroll
            for (int mt = 0; mt < 2; mt++) {
                int aoff = ((s * 4 + wm * 2 + mt) * 32 + lane) * 4;
                *(uint4*)ah[mt] = *(const uint4*)(bufA + aoff);
                *(uint4*)al[mt] = *(const uint4*)(bufA + ATERM_U + aoff);
            }
            #pragma unroll
            for (int nt = 0; nt < 4; nt++) {
                int boff = ((s * 16 + wn_ * 4 + nt) * 32 + lane) * 2;
                *(uint2*)bh[nt] = *(const uint2*)(bufB + boff);
                *(uint2*)bl[nt] = *(const uint2*)(bufB + BTERM_U + boff);
            }
            #pragma unroll
            for (int mt = 0; mt < 2; mt++)
                #pragma unroll
                for (int nt = 0; nt < 4; nt++) mma_f16(tmp[mt][nt], ah[mt], bh[nt]);   // hh
            #pragma unroll
            for (int mt = 0; mt < 2; mt++)
                #pragma unroll
                for (int nt = 0; nt < 4; nt++) mma_f16(tmp[mt][nt], ah[mt], bl[nt]);   // hl
            #pragma unroll
            for (int mt = 0; mt < 2; mt++)
                #pragma unroll
                for (int nt = 0; nt < 4; nt++) mma_f16(tmp[mt][nt], al[mt], bh[nt]);   // lh
        }

        // ---- convert xr = x(kb+1) -> A(kb+1) in buf[cur^1] ----
        if (kb < NKB - 1) {
            #pragma unroll
            for (int i = 0; i < 2; i++) {
                float e[4] = {xr[i].x, xr[i].y, xr[i].z, xr[i].w};
                #pragma unroll
                for (int h = 0; h < 2; h++) {
                    int kk = kq + i * 4 + 2 * h;
                    uint32_t hp, lp;
                    split2(e[2 * h] * XSCL, e[2 * h + 1] * XSCL, hp, lp);
                    int s   = kk >> 4;
                    int kp  = kk & 15;
                    int reg = ((kp >> 3) << 1) | (rr >> 3);
                    int ln  = (rr & 7) * 4 + ((kp >> 1) & 3);
                    int idx = ((s * 4 + amt) * 32 + ln) * 4 + reg;
                    bufN[idx]           = hp;
                    bufN[ATERM_U + idx] = lp;
                }
            }
        }
        // ---- prefetch x(kb+2) ----
        if (kb < NKB - 2) {
            const int k0 = (kb + 2) * KC;
            const float* xp = x + (size_t)(m0 + tok) * DDIM + k0 + kq;
            const float* wp = wskip + k0 + kq;
            #pragma unroll
            for (int i = 0; i < 2; i++) {
                xr[i] = *(const float4*)(xp + i * 4);
                float4 w4 = *(const float4*)(wp + i * 4);
                sk = fmaf(xr[i].x, w4.x, fmaf(xr[i].y, w4.y, fmaf(xr[i].z, w4.z, fmaf(xr[i].w, w4.w, sk))));
            }
        }
        // ---- fold tmp -> master (two-level accumulation) ----
        #pragma unroll
        for (int mt = 0; mt < 2; mt++)
            #pragma unroll
            for (int nt = 0; nt < 4; nt++)
                #pragma unroll
                for (int i = 0; i < 4; i++)
                    master[mt][nt][i] = __fadd_rn(master[mt][nt][i], tmp[mt][nt][i]);

        if (kb < NKB - 1) cp_wait();
        __syncthreads();
    }

    // ---- stage logits (unscale + bias) into ls ----
    #pragma unroll
    for (int mt = 0; mt < 2; mt++) {
        int r0 = wm * 32 + mt * 16 + (lane >> 2);
        #pragma unroll
        for (int nt = 0; nt < 4; nt++) {
            int c0 = wn_ * 32 + nt * 8 + (lane & 3) * 2;
            float b0 = (c0 < 64) ? __ldg(br + c0) : __ldg(bn + c0 - 64);
            float b1 = (c0 + 1 < 64) ? __ldg(br + c0 + 1) : __ldg(bn + c0 + 1 - 64);
            ls[r0][c0]         = __fadd_rn(master[mt][nt][0] * INV_SCL, b0);
            ls[r0][c0 + 1]     = __fadd_rn(master[mt][nt][1] * INV_SCL, b1);
            ls[r0 + 8][c0]     = __fadd_rn(master[mt][nt][2] * INV_SCL, b0);
            ls[r0 + 8][c0 + 1] = __fadd_rn(master[mt][nt][3] * INV_SCL, b1);
        }
    }
    // skip gate: combine 4 quarter-partials (lanes tid^1, tid^2)
    {
        sk += __shfl_xor_sync(0xffffffffu, sk, 1);
        sk += __shfl_xor_sync(0xffffffffu, sk, 2);
        if ((tid & 3) == 0) ls[tok][128] = __fadd_rn(sk, __ldg(bskip));
    }
    __syncthreads();

    // ---- noisy logits: 64 tok x 64 experts over 256 threads ----
    #pragma unroll
    for (int i = 0; i < 16; i++) {
        int fid = tid + i * NTHREADS;
        int tk = fid >> 6;
        int e  = fid & 63;
        float  lg = ls[tk][e];
        float  no = ls[tk][64 + e];
        double nd = (double)no;
        float  sp = (float)(fmax(nd, 0.0) + log1p(exp(-fabs(nd))));
        float  ev = __ldg(eps + (size_t)(m0 + tk) * NEXP + e);
        ls[tk][e] = __fadd_rn(lg, __fmul_rn(ev, sp));
    }
    __syncthreads();

    // ---- top-8 + softmax (one thread per token) ----
    if (tid < BM) {
        const int tk = tid;
        float vals[TOPK]; int idxs[TOPK];
        for (int k = 0; k < TOPK; k++) {
            float best = -3.402823466e38f; int bi = 0;
            for (int e = 0; e < NEXP; e++) {
                float v = ls[tk][e];
                if (v > best) { best = v; bi = e; }
            }
            vals[k] = best; idxs[k] = bi;
            ls[tk][bi] = -3.402823466e38f;
        }
        float mx = vals[0];
        float gsv[TOPK]; float s = 0.f;
        #pragma unroll
        for (int k = 0; k < TOPK; k++) { gsv[k] = expf(vals[k] - mx); s += gsv[k]; }
        float inv = 1.f / s;
        for (int e = 0; e < NEXP; e++) ls[tk][e] = 0.f;
        #pragma unroll
        for (int k = 0; k < TOPK; k++) ls[tk][idxs[k]] = gsv[k] * inv;
        #pragma unroll
        for (int k = 0; k < TOPK; k++) ls[tk][64 + k] = (float)idxs[k];
    }
    __syncthreads();

    // ---- cooperative coalesced stores ----
    #pragma unroll
    for (int i = 0; i < 16; i++) {
        int fid = tid + i * NTHREADS;
        int tk = fid >> 6;
        int e  = fid & 63;
        out_router[(size_t)(m0 + tk) * NEXP + e] = ls[tk][e];
    }
    #pragma unroll
    for (int i = 0; i < 2; i++) {
        int fid = tid + i * NTHREADS;
        int tk = fid >> 3;
        int k  = fid & 7;
        out_idx[(size_t)(m0 + tk) * TOPK + k] = ls[tk][64 + k];
    }
    if (tid < BM) {
        float z = ls[tid][128];
        out_skip[m0 + tid] = 1.f / (1.f + expf(-z));
    }
}

extern "C" void kernel_launch(void* const* d_in, const int* in_sizes, int n_in,
                              void* d_out, int out_size)
{
    const float* x     = (const float*)d_in[0];
    const float* eps   = (const float*)d_in[1];
    const float* wr    = (const float*)d_in[2];
    const float* br    = (const float*)d_in[3];
    const float* wn    = (const float*)d_in[4];
    const float* bn    = (const float*)d_in[5];
    const float* wskip = (const float*)d_in[6];
    const float* bskip = (const float*)d_in[7];

    float* out        = (float*)d_out;
    float* out_router = out;                                   // [32768, 64]
    float* out_idx    = out + (size_t)MTOK * NEXP;             // [32768, 8] as float
    float* out_skip   = out_idx + (size_t)MTOK * TOPK;         // [32768, 1]

    wprep_kernel<<<(NCOLS * DDIM / 2 + 255) / 256, 256>>>(wr, wn);

    cudaFuncSetAttribute(router_mma_kernel, cudaFuncAttributeMaxDynamicSharedMemorySize, SMEM_TOTAL);
    router_mma_kernel<<<MTOK / BM, NTHREADS, SMEM_TOTAL>>>(
        x, eps, br, bn, wskip, bskip, out_router, out_idx, out_skip);
}